// round 9
// baseline (speedup 1.0000x reference)
#include <cuda_runtime.h>

#define HH 512
#define WW 512
#define NC 48
#define NP (HH*WW)
#define CPT 6    // channels per thread
#define GPP 8    // channel-groups per pixel strip
#define RPB 4    // rows per block (sliding window)
#define FULLM 0xFFFFFFFFu

// ---- scratch (static device globals: allocation-free, graph-safe) ----
__device__ float g_a[NC*NP];
__device__ float g_b[NC*NP];
__device__ float g_s0[NP];
__device__ float g_s1[NP];
__device__ float g_aux[12*NP];   // 12 planar scalar coeff planes

// ---- K0: per-pixel stencil weights (periodic rolls on Dt), folded /dg, 0.5*hinv,
//          zero-pad masks; planar output ----
__global__ void k_aux(const float* __restrict__ Dt, const float* __restrict__ dg,
                      const float* __restrict__ hinv) {
    int p = blockIdx.x * blockDim.x + threadIdx.x;
    if (p >= NP) return;
    int h = p >> 9, w = p & 511;
    int hm = (h - 1) & 511, hp = (h + 1) & 511;
    int wm = (w - 1) & 511, wp = (w + 1) & 511;
    #define DTA(hh,ww) Dt[(((hh)<<9)+(ww))*3+0]
    #define DTC(hh,ww) Dt[(((hh)<<9)+(ww))*3+1]
    #define DTB(hh,ww) Dt[(((hh)<<9)+(ww))*3+2]
    float a00 = DTA(h,w),  c00 = DTC(h,w),  b00 = DTB(h,w);
    float a_hm = DTA(hm,w), b_hm = DTB(hm,w);
    float a_hp = DTA(hp,w), b_hp = DTB(hp,w);
    float c_wm = DTC(h,wm), b_wm = DTB(h,wm);
    float c_wp = DTC(h,wp), b_wp = DTB(h,wp);
    float b_mm = DTB(hm,wm);
    float b_mp = DTB(hm,wp);
    float b_pm = DTB(hp,wm);
    float b_pp = DTB(hp,wp);
    #undef DTA
    #undef DTC
    #undef DTB
    float A0 = (fabsf(b_pm) - b_pm + fabsf(b00) - b00) * 0.25f;
    float A1 = (c_wm + c00 - fabsf(b_wm) - fabsf(b00)) * 0.5f;
    float A2 = (fabsf(b_mm) + b_mm + fabsf(b00) + b00) * 0.25f;
    float A3 = (a_hp + a00 - fabsf(b_hp) - fabsf(b00)) * 0.5f;
    float A4 = -(a_hp + 2.0f*a00 + a_hm) * 0.5f
               - (fabsf(b_pm) - b_pm + fabsf(b_mm) + b_mm) * 0.25f
               - (fabsf(b_pp) + b_pp + fabsf(b_mp) - b_mp) * 0.25f
               + (fabsf(b_hp) + fabsf(b_hm) + fabsf(b_wp) + fabsf(b_wm) + 2.0f*fabsf(b00)) * 0.5f
               - (c_wp + 2.0f*c00 + c_wm) * 0.5f;
    float A5 = (a_hm + a00 - fabsf(b_hm) - fabsf(b00)) * 0.5f;
    float A6 = (fabsf(b_pp) + b_pp + fabsf(b00) + b00) * 0.25f;
    float A7 = (c_wp + c00 - fabsf(b_wp) - fabsf(b00)) * 0.5f;
    float A8 = (fabsf(b_mp) - b_mp + fabsf(b00) - b00) * 0.25f;

    float inv_dg = 1.0f / dg[p];
    float mhm = (h > 0)      ? 1.0f : 0.0f;
    float mhp = (h < HH - 1) ? 1.0f : 0.0f;
    float mwm = (w > 0)      ? 1.0f : 0.0f;
    float mwp = (w < WW - 1) ? 1.0f : 0.0f;

    g_aux[0*NP+p]  = A0 * inv_dg * mhm * mwm;
    g_aux[1*NP+p]  = A1 * inv_dg * mhm;
    g_aux[2*NP+p]  = A2 * inv_dg * mhm * mwp;
    g_aux[3*NP+p]  = A3 * inv_dg * mwm;
    g_aux[4*NP+p]  = A4 * inv_dg;
    g_aux[5*NP+p]  = A5 * inv_dg * mwp;
    g_aux[6*NP+p]  = A6 * inv_dg * mhp * mwm;
    g_aux[7*NP+p]  = A7 * inv_dg * mhp;
    g_aux[8*NP+p]  = A8 * inv_dg * mhp * mwp;
    g_aux[9*NP+p]  = 0.5f * hinv[p*3+0];
    g_aux[10*NP+p] = 0.5f * hinv[p*3+1];
    g_aux[11*NP+p] =        hinv[p*3+2];
}

// ---- K1: coalesced smem-tile transpose v -> planar g_a, + s0 = logsumexp ----
__global__ void __launch_bounds__(256) k_trans(const float* __restrict__ v) {
    __shared__ float sm[64*49];        // 64 px x 48 ch, pitch 49 (odd: conflict-free cols)
    __shared__ float red[4][64];
    int tid = threadIdx.x;
    int p0 = blockIdx.x * 64;
    const float4* src = (const float4*)v + (size_t)blockIdx.x * 768;
    #pragma unroll
    for (int i = 0; i < 3; i++) {
        int f4 = i * 256 + tid;
        float4 t = src[f4];
        int off = f4 * 4;
        int px = off / 48;
        int ch = off % 48;
        float* d = &sm[px*49 + ch];
        d[0] = t.x; d[1] = t.y; d[2] = t.z; d[3] = t.w;
    }
    __syncthreads();
    int px = tid & 63;
    int cg = tid >> 6;                 // 0..3, 12 channels each
    int p  = p0 + px;
    float vv[12];
    float m = -3.402823466e38f;
    #pragma unroll
    for (int j = 0; j < 12; j++) {
        vv[j] = sm[px*49 + cg*12 + j];
        m = fmaxf(m, vv[j]);
        g_a[(size_t)(cg*12 + j)*NP + p] = vv[j];
    }
    red[cg][px] = m;
    __syncthreads();
    m = fmaxf(fmaxf(red[0][px], red[1][px]), fmaxf(red[2][px], red[3][px]));
    float es = 0.0f;
    #pragma unroll
    for (int j = 0; j < 12; j++) es += __expf(vv[j] - m);
    __syncthreads();
    red[cg][px] = es;
    __syncthreads();
    if (cg == 0) {
        float sum = red[0][px] + red[1][px] + red[2][px] + red[3][px];
        g_s0[p] = m + __logf(sum);
    }
}

// ---- K2: fused Euler step; 64px x 4row tile, register sliding window.
//          Each thread: 2 horiz pixels x 6 channels, rows r-1/r/r+1 in regs. ----
__global__ void __launch_bounds__(32*GPP, 3) k_step(int ssel, int last,
                                                    float* __restrict__ out_ilv) {
    __shared__ float2 red0[GPP][32];
    __shared__ float2 red1[GPP][32];
    __shared__ float2 red2[GPP][32];

    int tx = threadIdx.x;
    int ty = threadIdx.y;
    int c0 = ty * CPT;

    int wbase = (blockIdx.x & 7) << 6;
    int h0 = (blockIdx.x >> 3) * RPB;
    int w = wbase + 2 * tx;
    int hcol = (tx == 0) ? ((wbase - 1) & 511) : ((wbase + 64) & 511);
    bool edge = (tx == 0) || (tx == 31);

    const float* x  = (ssel == 1) ? (const float*)g_a : (const float*)g_b;
    float* xo       = (ssel == 1) ? g_b : g_a;
    const float* si = (ssel == 1) ? (const float*)g_s0 : (const float*)g_s1;
    float* so       = (ssel == 1) ? g_s1 : g_s0;

    // prime the window: rows h0-1 (Tm) and h0 (T0)
    float2 Tm[CPT], T0[CPT], Tp[CPT];
    {
        int bm = ((h0 - 1) & 511) << 9;
        int b0 = h0 << 9;
        #pragma unroll
        for (int c = 0; c < CPT; c++) {
            const float* xc = x + (size_t)(c0 + c) * NP;
            Tm[c] = *(const float2*)&xc[bm + w];
            T0[c] = *(const float2*)&xc[b0 + w];
        }
    }

    #pragma unroll
    for (int r = 0; r < RPB; r++) {
        int hcur = h0 + r;
        int b0 = hcur << 9;
        int bm = ((hcur - 1) & 511) << 9;
        int bp = ((hcur + 1) & 511) << 9;
        int pA = b0 + w;

        // load next row
        #pragma unroll
        for (int c = 0; c < CPT; c++) {
            const float* xc = x + (size_t)(c0 + c) * NP;
            Tp[c] = *(const float2*)&xc[bp + w];
        }
        // per-row coefficients + s
        float2 C[12];
        #pragma unroll
        for (int k = 0; k < 12; k++)
            C[k] = *(const float2*)&g_aux[k*NP + pA];
        float2 s2  = *(const float2*)&si[pA];
        float2 sp2 = *(const float2*)&si[bp + w];
        float srx  = si[b0 + ((w + 2) & 511)];
        float dsxA = sp2.x - s2.x, dsxB = sp2.y - s2.y;
        float dsyA = s2.y  - s2.x, dsyB = srx - s2.y;

        float2 val[CPT];
        float vsumA = 0.0f, vsumB = 0.0f;
        #pragma unroll
        for (int c = 0; c < CPT; c++) {
            const float* xc = x + (size_t)(c0 + c) * NP;
            float hm_ = 0.0f, h0_ = 0.0f, hp_ = 0.0f;
            if (edge) {
                hm_ = xc[bm + hcol];
                h0_ = xc[b0 + hcol];
                hp_ = xc[bp + hcol];
            }
            float2 Mm = Tm[c], M0 = T0[c], Mp = Tp[c];
            float Lm = __shfl_up_sync(FULLM, Mm.y, 1); if (tx == 0) Lm = hm_;
            float L0 = __shfl_up_sync(FULLM, M0.y, 1); if (tx == 0) L0 = h0_;
            float Lp = __shfl_up_sync(FULLM, Mp.y, 1); if (tx == 0) Lp = hp_;
            float Rm = __shfl_down_sync(FULLM, Mm.x, 1); if (tx == 31) Rm = hm_;
            float R0 = __shfl_down_sync(FULLM, M0.x, 1); if (tx == 31) R0 = h0_;
            float Rp = __shfl_down_sync(FULLM, Mp.x, 1); if (tx == 31) Rp = hp_;

            // pixel A
            float accA = C[4].x * M0.x;
            accA = fmaf(C[0].x, Lm,   accA);
            accA = fmaf(C[1].x, Mm.x, accA);
            accA = fmaf(C[2].x, Mm.y, accA);
            accA = fmaf(C[3].x, L0,   accA);
            accA = fmaf(C[5].x, M0.y, accA);
            accA = fmaf(C[6].x, Lp,   accA);
            accA = fmaf(C[7].x, Mp.x, accA);
            accA = fmaf(C[8].x, Mp.y, accA);
            float vxA = (Mp.x - M0.x) - dsxA;
            float vyA = (M0.y - M0.x) - dsyA;
            accA = fmaf(fmaf(C[11].x, vyA, C[9].x * vxA), vxA, accA);
            accA = fmaf(C[10].x, vyA * vyA, accA);
            accA = fmaf(0.1f, M0.x, accA);

            // pixel B
            float accB = C[4].y * M0.y;
            accB = fmaf(C[0].y, Mm.x, accB);
            accB = fmaf(C[1].y, Mm.y, accB);
            accB = fmaf(C[2].y, Rm,   accB);
            accB = fmaf(C[3].y, M0.x, accB);
            accB = fmaf(C[5].y, R0,   accB);
            accB = fmaf(C[6].y, Mp.x, accB);
            accB = fmaf(C[7].y, Mp.y, accB);
            accB = fmaf(C[8].y, Rp,   accB);
            float vxB = (Mp.y - M0.y) - dsxB;
            float vyB = (R0   - M0.y) - dsyB;
            accB = fmaf(fmaf(C[11].y, vyB, C[9].y * vxB), vxB, accB);
            accB = fmaf(C[10].y, vyB * vyB, accB);
            accB = fmaf(0.1f, M0.y, accB);

            val[c].x = accA; val[c].y = accB;
            vsumA += accA; vsumB += accB;
        }

        // mean reduction
        red0[ty][tx].x = vsumA;
        red0[ty][tx].y = vsumB;
        __syncthreads();
        float meanA = 0.0f, meanB = 0.0f;
        #pragma unroll
        for (int g = 0; g < GPP; g++) {
            meanA += red0[g][tx].x;
            meanB += red0[g][tx].y;
        }
        meanA *= (1.0f / 48.0f);
        meanB *= (1.0f / 48.0f);

        // Euler update (center T0 is live in registers)
        #pragma unroll
        for (int c = 0; c < CPT; c++) {
            float tA = val[c].x - meanA;
            float tB = val[c].y - meanB;
            tA = fminf(fmaxf(tA, -1e8f), 1e8f);
            tB = fminf(fmaxf(tB, -1e8f), 1e8f);
            val[c].x = fmaf(0.2f, tA, T0[c].x);
            val[c].y = fmaf(0.2f, tB, T0[c].y);
        }

        if (!last) {
            float mA = val[0].x, mB = val[0].y;
            #pragma unroll
            for (int c = 1; c < CPT; c++) {
                mA = fmaxf(mA, val[c].x);
                mB = fmaxf(mB, val[c].y);
            }
            red1[ty][tx].x = mA;
            red1[ty][tx].y = mB;
            #pragma unroll
            for (int c = 0; c < CPT; c++)
                *(float2*)&xo[(size_t)(c0 + c) * NP + pA] = val[c];
            __syncthreads();
            mA = red1[0][tx].x; mB = red1[0][tx].y;
            #pragma unroll
            for (int g = 1; g < GPP; g++) {
                mA = fmaxf(mA, red1[g][tx].x);
                mB = fmaxf(mB, red1[g][tx].y);
            }
            float esA = 0.0f, esB = 0.0f;
            #pragma unroll
            for (int c = 0; c < CPT; c++) {
                esA += __expf(val[c].x - mA);
                esB += __expf(val[c].y - mB);
            }
            red2[ty][tx].x = esA;
            red2[ty][tx].y = esB;
            __syncthreads();
            if (ty == 0) {
                float sumA = 0.0f, sumB = 0.0f;
                #pragma unroll
                for (int g = 0; g < GPP; g++) {
                    sumA += red2[g][tx].x;
                    sumB += red2[g][tx].y;
                }
                float2 os;
                os.x = mA + __logf(sumA);
                os.y = mB + __logf(sumB);
                *(float2*)&so[pA] = os;
            }
        } else {
            float2* oA = (float2*)(out_ilv + (size_t)pA * NC + c0);
            float2* oB = (float2*)(out_ilv + (size_t)(pA + 1) * NC + c0);
            #pragma unroll
            for (int q = 0; q < 3; q++) {
                float2 a, b;
                a.x = val[q*2+0].x; a.y = val[q*2+1].x;
                b.x = val[q*2+0].y; b.y = val[q*2+1].y;
                oA[q] = a;
                oB[q] = b;
            }
            __syncthreads();   // keep red0 reuse safe across rows in last kernel too
        }

        // rotate window
        #pragma unroll
        for (int c = 0; c < CPT; c++) {
            Tm[c] = T0[c];
            T0[c] = Tp[c];
        }
    }
}

extern "C" void kernel_launch(void* const* d_in, const int* in_sizes, int n_in,
                              void* d_out, int out_size) {
    const float* v    = (const float*)d_in[0];
    const float* Dt   = (const float*)d_in[1];
    const float* dg   = (const float*)d_in[2];
    const float* hinv = (const float*)d_in[3];
    float* out = (float*)d_out;

    k_aux<<<NP / 256, 256>>>(Dt, dg, hinv);
    k_trans<<<NP / 64, 256>>>(v);

    dim3 blk(32, GPP);
    int grid = (HH / RPB) * 8;   // 1024 blocks, 64px x 4row tiles
    k_step<<<grid, blk>>>(1, 0, out);
    k_step<<<grid, blk>>>(2, 0, out);
    k_step<<<grid, blk>>>(1, 0, out);
    k_step<<<grid, blk>>>(2, 0, out);
    k_step<<<grid, blk>>>(1, 1, out);
}

// round 10
// speedup vs baseline: 1.2079x; 1.2079x over previous
#include <cuda_runtime.h>

#define HH 512
#define WW 512
#define NC 48
#define NP (HH*WW)
#define NQ 12      // channel quads
#define FULLM 0xFFFFFFFFu

// ---- scratch (static device globals: allocation-free, graph-safe) ----
// channel-quad planes: plane q holds float4 = channels 4q..4q+3, at g4[q*NP + p]
__device__ float4 g4a[NQ*NP];
__device__ float4 g4b[NQ*NP];
__device__ float  g_s0[NP];
__device__ float  g_s1[NP];
__device__ float4 g_aux4[3*NP];   // [p]=(A0..A3), [NP+p]=(A4..A7), [2NP+p]=(A8,ha,hb,hc)

// ---- K0: fused init: stencil weights + transpose v -> quad planes + s0 ----
__global__ void __launch_bounds__(256) k_init(const float* __restrict__ v,
                                              const float* __restrict__ Dt,
                                              const float* __restrict__ dg,
                                              const float* __restrict__ hinv) {
    int p = blockIdx.x * blockDim.x + threadIdx.x;
    if (p >= NP) return;
    int h = p >> 9, w = p & 511;
    int hm = (h - 1) & 511, hp = (h + 1) & 511;
    int wm = (w - 1) & 511, wp = (w + 1) & 511;
    #define DTA(hh,ww) Dt[(((hh)<<9)+(ww))*3+0]
    #define DTC(hh,ww) Dt[(((hh)<<9)+(ww))*3+1]
    #define DTB(hh,ww) Dt[(((hh)<<9)+(ww))*3+2]
    float a00 = DTA(h,w),  c00 = DTC(h,w),  b00 = DTB(h,w);
    float a_hm = DTA(hm,w), b_hm = DTB(hm,w);
    float a_hp = DTA(hp,w), b_hp = DTB(hp,w);
    float c_wm = DTC(h,wm), b_wm = DTB(h,wm);
    float c_wp = DTC(h,wp), b_wp = DTB(h,wp);
    float b_mm = DTB(hm,wm);
    float b_mp = DTB(hm,wp);
    float b_pm = DTB(hp,wm);
    float b_pp = DTB(hp,wp);
    #undef DTA
    #undef DTC
    #undef DTB
    float A0 = (fabsf(b_pm) - b_pm + fabsf(b00) - b00) * 0.25f;
    float A1 = (c_wm + c00 - fabsf(b_wm) - fabsf(b00)) * 0.5f;
    float A2 = (fabsf(b_mm) + b_mm + fabsf(b00) + b00) * 0.25f;
    float A3 = (a_hp + a00 - fabsf(b_hp) - fabsf(b00)) * 0.5f;
    float A4 = -(a_hp + 2.0f*a00 + a_hm) * 0.5f
               - (fabsf(b_pm) - b_pm + fabsf(b_mm) + b_mm) * 0.25f
               - (fabsf(b_pp) + b_pp + fabsf(b_mp) - b_mp) * 0.25f
               + (fabsf(b_hp) + fabsf(b_hm) + fabsf(b_wp) + fabsf(b_wm) + 2.0f*fabsf(b00)) * 0.5f
               - (c_wp + 2.0f*c00 + c_wm) * 0.5f;
    float A5 = (a_hm + a00 - fabsf(b_hm) - fabsf(b00)) * 0.5f;
    float A6 = (fabsf(b_pp) + b_pp + fabsf(b00) + b00) * 0.25f;
    float A7 = (c_wp + c00 - fabsf(b_wp) - fabsf(b00)) * 0.5f;
    float A8 = (fabsf(b_mp) - b_mp + fabsf(b00) - b00) * 0.25f;

    float inv_dg = 1.0f / dg[p];
    float mhm = (h > 0)      ? 1.0f : 0.0f;
    float mhp = (h < HH - 1) ? 1.0f : 0.0f;
    float mwm = (w > 0)      ? 1.0f : 0.0f;
    float mwp = (w < WW - 1) ? 1.0f : 0.0f;

    float4 q0, q1, q2;
    q0.x = A0 * inv_dg * mhm * mwm;
    q0.y = A1 * inv_dg * mhm;
    q0.z = A2 * inv_dg * mhm * mwp;
    q0.w = A3 * inv_dg * mwm;
    q1.x = A4 * inv_dg;
    q1.y = A5 * inv_dg * mwp;
    q1.z = A6 * inv_dg * mhp * mwm;
    q1.w = A7 * inv_dg * mhp;
    q2.x = A8 * inv_dg * mhp * mwp;
    q2.y = 0.5f * hinv[p*3+0];
    q2.z = 0.5f * hinv[p*3+1];
    q2.w =        hinv[p*3+2];
    g_aux4[p]        = q0;
    g_aux4[NP + p]   = q1;
    g_aux4[2*NP + p] = q2;

    // transpose v (already quad-contiguous per pixel) + logsumexp
    const float4* xp = (const float4*)v + (size_t)p * NQ;
    float4 t[NQ];
    float m = -3.402823466e38f;
    #pragma unroll
    for (int q = 0; q < NQ; q++) {
        t[q] = xp[q];
        m = fmaxf(m, fmaxf(fmaxf(t[q].x, t[q].y), fmaxf(t[q].z, t[q].w)));
    }
    float sum = 0.0f;
    #pragma unroll
    for (int q = 0; q < NQ; q++) {
        sum += __expf(t[q].x - m) + __expf(t[q].y - m)
             + __expf(t[q].z - m) + __expf(t[q].w - m);
        g4a[(size_t)q*NP + p] = t[q];
    }
    g_s0[p] = m + __logf(sum);
}

// ---- K2: fused Euler step; 1 thread = 1 pixel x 4 channels (one float4 plane).
//          Block = 32 px x 12 quad-groups; 12-way smem reductions. ----
__global__ void __launch_bounds__(384, 2) k_step(int ssel, int last,
                                                 float* __restrict__ out_ilv) {
    __shared__ float red0[NQ][32];
    __shared__ float red1[NQ][32];
    __shared__ float red2[NQ][32];

    int tx = threadIdx.x;           // pixel within 32-px strip
    int ty = threadIdx.y;           // channel quad (0..11)

    int h = blockIdx.x >> 4;             // 16 strips per row
    int w = ((blockIdx.x & 15) << 5) + tx;
    int hm = (h - 1) & 511, hp = (h + 1) & 511;
    int b0 = h << 9, bm = hm << 9, bp = hp << 9;
    int wm = (w - 1) & 511, wp = (w + 1) & 511;
    int p = b0 + w;

    const float4* x = (ssel == 1) ? (const float4*)g4a : (const float4*)g4b;
    float4* xo      = (ssel == 1) ? g4b : g4a;
    const float* si = (ssel == 1) ? (const float*)g_s0 : (const float*)g_s1;
    float* so       = (ssel == 1) ? g_s1 : g_s0;

    float4 q0 = g_aux4[p];
    float4 q1 = g_aux4[NP + p];
    float4 q2 = g_aux4[2*NP + p];
    float A0 = q0.x, A1 = q0.y, A2 = q0.z, A3 = q0.w;
    float A4 = q1.x, A5 = q1.y, A6 = q1.z, A7 = q1.w;
    float A8 = q2.x, ha = q2.y, hb = q2.z, hc = q2.w;

    float sc  = si[p];
    float dsx = si[bp + w] - sc;
    float dsy = si[b0 + wp] - sc;

    const float4* xq = x + (size_t)ty * NP;
    float4 tmm = xq[bm + wm], tm0 = xq[bm + w], tmp_ = xq[bm + wp];
    float4 t0m = xq[b0 + wm], t00 = xq[b0 + w], t0p  = xq[b0 + wp];
    float4 tpm = xq[bp + wm], tp0 = xq[bp + w], tpp  = xq[bp + wp];

    float4 val;
    #define DO(f) { \
        float acc = A4 * t00.f; \
        acc = fmaf(A0, tmm.f, acc); \
        acc = fmaf(A1, tm0.f, acc); \
        acc = fmaf(A2, tmp_.f, acc); \
        acc = fmaf(A3, t0m.f, acc); \
        acc = fmaf(A5, t0p.f, acc); \
        acc = fmaf(A6, tpm.f, acc); \
        acc = fmaf(A7, tp0.f, acc); \
        acc = fmaf(A8, tpp.f, acc); \
        float vx = (tp0.f - t00.f) - dsx; \
        float vy = (t0p.f - t00.f) - dsy; \
        acc = fmaf(fmaf(hc, vy, ha * vx), vx, acc); \
        acc = fmaf(hb, vy * vy, acc); \
        acc = fmaf(0.1f, t00.f, acc); \
        val.f = acc; }
    DO(x) DO(y) DO(z) DO(w)
    #undef DO

    // 12-way mean reduction
    red0[ty][tx] = val.x + val.y + val.z + val.w;
    __syncthreads();
    float mean = 0.0f;
    #pragma unroll
    for (int g = 0; g < NQ; g++) mean += red0[g][tx];
    mean *= (1.0f / 48.0f);

    // Euler update (center t00 live in regs)
    #define DO2(f) { \
        float t = val.f - mean; \
        t = fminf(fmaxf(t, -1e8f), 1e8f); \
        val.f = fmaf(0.2f, t, t00.f); }
    DO2(x) DO2(y) DO2(z) DO2(w)
    #undef DO2

    if (!last) {
        float mloc = fmaxf(fmaxf(val.x, val.y), fmaxf(val.z, val.w));
        red1[ty][tx] = mloc;
        xo[(size_t)ty * NP + p] = val;
        __syncthreads();
        float m = red1[0][tx];
        #pragma unroll
        for (int g = 1; g < NQ; g++) m = fmaxf(m, red1[g][tx]);
        float es = __expf(val.x - m) + __expf(val.y - m)
                 + __expf(val.z - m) + __expf(val.w - m);
        red2[ty][tx] = es;
        __syncthreads();
        if (ty == 0) {
            float sum = 0.0f;
            #pragma unroll
            for (int g = 0; g < NQ; g++) sum += red2[g][tx];
            so[p] = m + __logf(sum);
        }
    } else {
        // interleaved output: quad ty of pixel p at out[p*48 + ty*4] (16B aligned)
        *(float4*)(out_ilv + (size_t)p * NC + ty * 4) = val;
    }
}

extern "C" void kernel_launch(void* const* d_in, const int* in_sizes, int n_in,
                              void* d_out, int out_size) {
    const float* v    = (const float*)d_in[0];
    const float* Dt   = (const float*)d_in[1];
    const float* dg   = (const float*)d_in[2];
    const float* hinv = (const float*)d_in[3];
    float* out = (float*)d_out;

    k_init<<<NP / 256, 256>>>(v, Dt, dg, hinv);

    dim3 blk(32, NQ);
    int grid = NP / 32;   // 8192
    k_step<<<grid, blk>>>(1, 0, out);
    k_step<<<grid, blk>>>(2, 0, out);
    k_step<<<grid, blk>>>(1, 0, out);
    k_step<<<grid, blk>>>(2, 0, out);
    k_step<<<grid, blk>>>(1, 1, out);
}

// round 11
// speedup vs baseline: 1.4210x; 1.1764x over previous
#include <cuda_runtime.h>

#define HH 512
#define WW 512
#define NC 48
#define NP (HH*WW)
#define NQ 12
#define CPT 6    // channels per thread
#define GPP 8    // channel-groups (warps) per pixel strip
#define PXB 32   // pixels per block

// ---- scratch (static device globals: allocation-free, graph-safe) ----
__device__ float g_a[NC*NP];
__device__ float g_b[NC*NP];
__device__ float g_s0[NP];
__device__ float g_s1[NP];
__device__ float g_aux[12*NP];   // 12 planar scalar coeff planes

// ---- K0: per-pixel stencil weights (periodic rolls on Dt), folded /dg, 0.5*hinv,
//          zero-pad masks; scalar planar output ----
__global__ void k_aux(const float* __restrict__ Dt, const float* __restrict__ dg,
                      const float* __restrict__ hinv) {
    int p = blockIdx.x * blockDim.x + threadIdx.x;
    if (p >= NP) return;
    int h = p >> 9, w = p & 511;
    int hm = (h - 1) & 511, hp = (h + 1) & 511;
    int wm = (w - 1) & 511, wp = (w + 1) & 511;
    #define DTA(hh,ww) Dt[(((hh)<<9)+(ww))*3+0]
    #define DTC(hh,ww) Dt[(((hh)<<9)+(ww))*3+1]
    #define DTB(hh,ww) Dt[(((hh)<<9)+(ww))*3+2]
    float a00 = DTA(h,w),  c00 = DTC(h,w),  b00 = DTB(h,w);
    float a_hm = DTA(hm,w), b_hm = DTB(hm,w);
    float a_hp = DTA(hp,w), b_hp = DTB(hp,w);
    float c_wm = DTC(h,wm), b_wm = DTB(h,wm);
    float c_wp = DTC(h,wp), b_wp = DTB(h,wp);
    float b_mm = DTB(hm,wm);
    float b_mp = DTB(hm,wp);
    float b_pm = DTB(hp,wm);
    float b_pp = DTB(hp,wp);
    #undef DTA
    #undef DTC
    #undef DTB
    float A0 = (fabsf(b_pm) - b_pm + fabsf(b00) - b00) * 0.25f;
    float A1 = (c_wm + c00 - fabsf(b_wm) - fabsf(b00)) * 0.5f;
    float A2 = (fabsf(b_mm) + b_mm + fabsf(b00) + b00) * 0.25f;
    float A3 = (a_hp + a00 - fabsf(b_hp) - fabsf(b00)) * 0.5f;
    float A4 = -(a_hp + 2.0f*a00 + a_hm) * 0.5f
               - (fabsf(b_pm) - b_pm + fabsf(b_mm) + b_mm) * 0.25f
               - (fabsf(b_pp) + b_pp + fabsf(b_mp) - b_mp) * 0.25f
               + (fabsf(b_hp) + fabsf(b_hm) + fabsf(b_wp) + fabsf(b_wm) + 2.0f*fabsf(b00)) * 0.5f
               - (c_wp + 2.0f*c00 + c_wm) * 0.5f;
    float A5 = (a_hm + a00 - fabsf(b_hm) - fabsf(b00)) * 0.5f;
    float A6 = (fabsf(b_pp) + b_pp + fabsf(b00) + b00) * 0.25f;
    float A7 = (c_wp + c00 - fabsf(b_wp) - fabsf(b00)) * 0.5f;
    float A8 = (fabsf(b_mp) - b_mp + fabsf(b00) - b00) * 0.25f;

    float inv_dg = 1.0f / dg[p];
    float mhm = (h > 0)      ? 1.0f : 0.0f;
    float mhp = (h < HH - 1) ? 1.0f : 0.0f;
    float mwm = (w > 0)      ? 1.0f : 0.0f;
    float mwp = (w < WW - 1) ? 1.0f : 0.0f;

    g_aux[0*NP+p]  = A0 * inv_dg * mhm * mwm;
    g_aux[1*NP+p]  = A1 * inv_dg * mhm;
    g_aux[2*NP+p]  = A2 * inv_dg * mhm * mwp;
    g_aux[3*NP+p]  = A3 * inv_dg * mwm;
    g_aux[4*NP+p]  = A4 * inv_dg;
    g_aux[5*NP+p]  = A5 * inv_dg * mwp;
    g_aux[6*NP+p]  = A6 * inv_dg * mhp * mwm;
    g_aux[7*NP+p]  = A7 * inv_dg * mhp;
    g_aux[8*NP+p]  = A8 * inv_dg * mhp * mwp;
    g_aux[9*NP+p]  = 0.5f * hinv[p*3+0];
    g_aux[10*NP+p] = 0.5f * hinv[p*3+1];
    g_aux[11*NP+p] =        hinv[p*3+2];
}

// ---- K1: coalesced smem-tile transpose v -> planar g_a, + s0 = logsumexp ----
__global__ void __launch_bounds__(256) k_trans(const float* __restrict__ v) {
    __shared__ float sm[64*49];        // 64 px x 48 ch, pitch 49 (conflict-free)
    __shared__ float red[4][64];
    int tid = threadIdx.x;
    int p0 = blockIdx.x * 64;
    const float4* src = (const float4*)v + (size_t)blockIdx.x * 768;
    #pragma unroll
    for (int i = 0; i < 3; i++) {
        int f4 = i * 256 + tid;
        float4 t = src[f4];
        int off = f4 * 4;
        int px = off / 48;
        int ch = off % 48;
        float* d = &sm[px*49 + ch];
        d[0] = t.x; d[1] = t.y; d[2] = t.z; d[3] = t.w;
    }
    __syncthreads();
    int px = tid & 63;
    int cg = tid >> 6;                 // 0..3, 12 channels each
    int p  = p0 + px;
    float vv[12];
    float m = -3.402823466e38f;
    #pragma unroll
    for (int j = 0; j < 12; j++) {
        vv[j] = sm[px*49 + cg*12 + j];
        m = fmaxf(m, vv[j]);
        g_a[(size_t)(cg*12 + j)*NP + p] = vv[j];
    }
    red[cg][px] = m;
    __syncthreads();
    m = fmaxf(fmaxf(red[0][px], red[1][px]), fmaxf(red[2][px], red[3][px]));
    float es = 0.0f;
    #pragma unroll
    for (int j = 0; j < 12; j++) es += __expf(vv[j] - m);
    __syncthreads();
    red[cg][px] = es;
    __syncthreads();
    if (cg == 0) {
        float sum = red[0][px] + red[1][px] + red[2][px] + red[3][px];
        g_s0[p] = m + __logf(sum);
    }
}

// ---- K2: fused Euler step; 8 threads per pixel, 6 channels each (R5 config).
//          last==1: smem-staged coalesced interleaved output. ----
__global__ void __launch_bounds__(PXB*GPP, 5) k_step(int ssel, int last,
                                                     float* __restrict__ out_ilv) {
    __shared__ float red0[GPP][PXB];
    __shared__ float red1[GPP][PXB];
    __shared__ float red2[GPP][PXB];
    __shared__ float smo[PXB*49];    // 32 px x 48 ch staging, pitch 49

    int tx = threadIdx.x;           // pixel within block (0..31)
    int ty = threadIdx.y;           // channel group (0..7)
    int p  = blockIdx.x * PXB + tx;
    int c0 = ty * CPT;

    const float* x  = (ssel == 1) ? (const float*)g_a : (const float*)g_b;
    float* xo       = (ssel == 1) ? g_b : g_a;
    const float* si = (ssel == 1) ? (const float*)g_s0 : (const float*)g_s1;
    float* so       = (ssel == 1) ? g_s1 : g_s0;

    int h = p >> 9, w = p & 511;
    int hm = (h - 1) & 511, hp = (h + 1) & 511;
    int wm = (w - 1) & 511, wp = (w + 1) & 511;
    int i_mm = (hm << 9) + wm, i_m0 = (hm << 9) + w, i_mp = (hm << 9) + wp;
    int i_0m = (h  << 9) + wm,                       i_0p = (h  << 9) + wp;
    int i_pm = (hp << 9) + wm, i_p0 = (hp << 9) + w, i_pp = (hp << 9) + wp;

    float A0 = g_aux[0*NP+p], A1 = g_aux[1*NP+p], A2 = g_aux[2*NP+p];
    float A3 = g_aux[3*NP+p], A4 = g_aux[4*NP+p], A5 = g_aux[5*NP+p];
    float A6 = g_aux[6*NP+p], A7 = g_aux[7*NP+p], A8 = g_aux[8*NP+p];
    float ha = g_aux[9*NP+p], hb = g_aux[10*NP+p], hc = g_aux[11*NP+p];

    float sc  = si[p];
    float dsx = si[i_p0] - sc;
    float dsy = si[i_0p] - sc;

    float val[CPT];
    float cen[CPT];
    float vsum = 0.0f;
    #pragma unroll
    for (int c = 0; c < CPT; c++) {
        const float* xc = x + (size_t)(c0 + c) * NP;
        float t00 = xc[p];
        float tp0 = xc[i_p0];
        float t0p = xc[i_0p];
        float acc = A4 * t00;
        acc = fmaf(A0, xc[i_mm], acc);
        acc = fmaf(A1, xc[i_m0], acc);
        acc = fmaf(A2, xc[i_mp], acc);
        acc = fmaf(A3, xc[i_0m], acc);
        acc = fmaf(A5, t0p, acc);
        acc = fmaf(A6, xc[i_pm], acc);
        acc = fmaf(A7, tp0, acc);
        acc = fmaf(A8, xc[i_pp], acc);
        float vx = (tp0 - t00) - dsx;
        float vy = (t0p - t00) - dsy;
        acc = fmaf(fmaf(hc, vy, ha * vx), vx, acc);
        acc = fmaf(hb, vy * vy, acc);
        acc = fmaf(0.1f, t00, acc);
        val[c] = acc;
        cen[c] = t00;
        vsum += acc;
    }

    // 8-way mean reduction
    red0[ty][tx] = vsum;
    __syncthreads();
    float mean = 0.0f;
    #pragma unroll
    for (int g = 0; g < GPP; g++) mean += red0[g][tx];
    mean *= (1.0f / 48.0f);

    // Euler update
    #pragma unroll
    for (int c = 0; c < CPT; c++) {
        float t = val[c] - mean;
        t = fminf(fmaxf(t, -1e8f), 1e8f);
        val[c] = fmaf(0.2f, t, cen[c]);
    }

    if (!last) {
        float mloc = val[0];
        #pragma unroll
        for (int c = 1; c < CPT; c++) mloc = fmaxf(mloc, val[c]);
        red1[ty][tx] = mloc;
        #pragma unroll
        for (int c = 0; c < CPT; c++)
            xo[(size_t)(c0 + c) * NP + p] = val[c];
        __syncthreads();
        float m = red1[0][tx];
        #pragma unroll
        for (int g = 1; g < GPP; g++) m = fmaxf(m, red1[g][tx]);
        float es = 0.0f;
        #pragma unroll
        for (int c = 0; c < CPT; c++) es += __expf(val[c] - m);
        red2[ty][tx] = es;
        __syncthreads();
        if (ty == 0) {
            float sum = 0.0f;
            #pragma unroll
            for (int g = 0; g < GPP; g++) sum += red2[g][tx];
            so[p] = m + __logf(sum);
        }
    } else {
        // stage the 32px x 48ch tile in smem, then write coalesced float4s
        #pragma unroll
        for (int c = 0; c < CPT; c++)
            smo[tx*49 + c0 + c] = val[c];
        __syncthreads();
        int tid = ty * PXB + tx;        // 0..255
        float4* o4 = (float4*)(out_ilv + (size_t)blockIdx.x * PXB * NC);
        #pragma unroll
        for (int i = tid; i < (PXB*NC)/4; i += PXB*GPP) {
            int off = i * 4;             // 48 % 4 == 0: float4 stays within one pixel
            int px = off / NC;
            int ch = off % NC;
            const float* s4 = &smo[px*49 + ch];
            float4 t;
            t.x = s4[0]; t.y = s4[1]; t.z = s4[2]; t.w = s4[3];
            o4[i] = t;
        }
    }
}

extern "C" void kernel_launch(void* const* d_in, const int* in_sizes, int n_in,
                              void* d_out, int out_size) {
    const float* v    = (const float*)d_in[0];
    const float* Dt   = (const float*)d_in[1];
    const float* dg   = (const float*)d_in[2];
    const float* hinv = (const float*)d_in[3];
    float* out = (float*)d_out;

    k_aux<<<NP / 256, 256>>>(Dt, dg, hinv);
    k_trans<<<NP / 64, 256>>>(v);

    dim3 blk(PXB, GPP);
    int grid = NP / PXB;   // 8192
    k_step<<<grid, blk>>>(1, 0, out);
    k_step<<<grid, blk>>>(2, 0, out);
    k_step<<<grid, blk>>>(1, 0, out);
    k_step<<<grid, blk>>>(2, 0, out);
    k_step<<<grid, blk>>>(1, 1, out);
}

// round 12
// speedup vs baseline: 1.6654x; 1.1720x over previous
#include <cuda_runtime.h>

#define HH 512
#define WW 512
#define NC 48
#define NP (HH*WW)
#define CPT 6    // channels per thread
#define GPP 8    // channel-groups (warps) per pixel strip
#define PXW 64   // pixels per block (32 lanes x 2 px/thread)

// ---- scratch (static device globals: allocation-free, graph-safe) ----
__device__ float g_a[NC*NP];
__device__ float g_b[NC*NP];
__device__ float g_s0[NP];
__device__ float g_s1[NP];
__device__ float g_aux[12*NP];   // 12 planar scalar coeff planes

// ---- K0: fused init. Per 64-px block: coalesced transpose v -> planar g_a
//          + s0 = logsumexp, and (threads 0-63) stencil-weight precompute. ----
__global__ void __launch_bounds__(256) k_init(const float* __restrict__ v,
                                              const float* __restrict__ Dt,
                                              const float* __restrict__ dg,
                                              const float* __restrict__ hinv) {
    __shared__ float sm[64*49];        // 64 px x 48 ch, pitch 49 (conflict-free)
    __shared__ float red[4][64];
    int tid = threadIdx.x;
    int p0 = blockIdx.x * 64;

    // coalesced read of the 64px x 48ch tile
    const float4* src = (const float4*)v + (size_t)blockIdx.x * 768;
    #pragma unroll
    for (int i = 0; i < 3; i++) {
        int f4 = i * 256 + tid;
        float4 t = src[f4];
        int off = f4 * 4;
        int px = off / 48;
        int ch = off % 48;
        float* d = &sm[px*49 + ch];
        d[0] = t.x; d[1] = t.y; d[2] = t.z; d[3] = t.w;
    }

    // stencil-weight precompute: one pixel per thread for tid < 64
    if (tid < 64) {
        int p = p0 + tid;
        int h = p >> 9, w = p & 511;
        int hm = (h - 1) & 511, hp = (h + 1) & 511;
        int wm = (w - 1) & 511, wp = (w + 1) & 511;
        #define DTA(hh,ww) Dt[(((hh)<<9)+(ww))*3+0]
        #define DTC(hh,ww) Dt[(((hh)<<9)+(ww))*3+1]
        #define DTB(hh,ww) Dt[(((hh)<<9)+(ww))*3+2]
        float a00 = DTA(h,w),  c00 = DTC(h,w),  b00 = DTB(h,w);
        float a_hm = DTA(hm,w), b_hm = DTB(hm,w);
        float a_hp = DTA(hp,w), b_hp = DTB(hp,w);
        float c_wm = DTC(h,wm), b_wm = DTB(h,wm);
        float c_wp = DTC(h,wp), b_wp = DTB(h,wp);
        float b_mm = DTB(hm,wm);
        float b_mp = DTB(hm,wp);
        float b_pm = DTB(hp,wm);
        float b_pp = DTB(hp,wp);
        #undef DTA
        #undef DTC
        #undef DTB
        float A0 = (fabsf(b_pm) - b_pm + fabsf(b00) - b00) * 0.25f;
        float A1 = (c_wm + c00 - fabsf(b_wm) - fabsf(b00)) * 0.5f;
        float A2 = (fabsf(b_mm) + b_mm + fabsf(b00) + b00) * 0.25f;
        float A3 = (a_hp + a00 - fabsf(b_hp) - fabsf(b00)) * 0.5f;
        float A4 = -(a_hp + 2.0f*a00 + a_hm) * 0.5f
                   - (fabsf(b_pm) - b_pm + fabsf(b_mm) + b_mm) * 0.25f
                   - (fabsf(b_pp) + b_pp + fabsf(b_mp) - b_mp) * 0.25f
                   + (fabsf(b_hp) + fabsf(b_hm) + fabsf(b_wp) + fabsf(b_wm) + 2.0f*fabsf(b00)) * 0.5f
                   - (c_wp + 2.0f*c00 + c_wm) * 0.5f;
        float A5 = (a_hm + a00 - fabsf(b_hm) - fabsf(b00)) * 0.5f;
        float A6 = (fabsf(b_pp) + b_pp + fabsf(b00) + b00) * 0.25f;
        float A7 = (c_wp + c00 - fabsf(b_wp) - fabsf(b00)) * 0.5f;
        float A8 = (fabsf(b_mp) - b_mp + fabsf(b00) - b00) * 0.25f;

        float inv_dg = 1.0f / dg[p];
        float mhm = (h > 0)      ? 1.0f : 0.0f;
        float mhp = (h < HH - 1) ? 1.0f : 0.0f;
        float mwm = (w > 0)      ? 1.0f : 0.0f;
        float mwp = (w < WW - 1) ? 1.0f : 0.0f;

        g_aux[0*NP+p]  = A0 * inv_dg * mhm * mwm;
        g_aux[1*NP+p]  = A1 * inv_dg * mhm;
        g_aux[2*NP+p]  = A2 * inv_dg * mhm * mwp;
        g_aux[3*NP+p]  = A3 * inv_dg * mwm;
        g_aux[4*NP+p]  = A4 * inv_dg;
        g_aux[5*NP+p]  = A5 * inv_dg * mwp;
        g_aux[6*NP+p]  = A6 * inv_dg * mhp * mwm;
        g_aux[7*NP+p]  = A7 * inv_dg * mhp;
        g_aux[8*NP+p]  = A8 * inv_dg * mhp * mwp;
        g_aux[9*NP+p]  = 0.5f * hinv[p*3+0];
        g_aux[10*NP+p] = 0.5f * hinv[p*3+1];
        g_aux[11*NP+p] =        hinv[p*3+2];
    }
    __syncthreads();

    // planar writes + logsumexp from the smem tile
    int px = tid & 63;
    int cg = tid >> 6;                 // 0..3, 12 channels each
    int p  = p0 + px;
    float vv[12];
    float m = -3.402823466e38f;
    #pragma unroll
    for (int j = 0; j < 12; j++) {
        vv[j] = sm[px*49 + cg*12 + j];
        m = fmaxf(m, vv[j]);
        g_a[(size_t)(cg*12 + j)*NP + p] = vv[j];
    }
    red[cg][px] = m;
    __syncthreads();
    m = fmaxf(fmaxf(red[0][px], red[1][px]), fmaxf(red[2][px], red[3][px]));
    float es = 0.0f;
    #pragma unroll
    for (int j = 0; j < 12; j++) es += __expf(vv[j] - m);
    __syncthreads();
    red[cg][px] = es;
    __syncthreads();
    if (cg == 0) {
        float sum = red[0][px] + red[1][px] + red[2][px] + red[3][px];
        g_s0[p] = m + __logf(sum);
    }
}

// ---- K2: fused Euler step (steps 1..4); each thread = 2 horiz pixels x 6 ch.
//          Exact R6 hot-loop structure (fastest measured: 41.6us). ----
__global__ void __launch_bounds__(32*GPP, 3) k_step(int ssel) {
    __shared__ float2 red0[GPP][32];
    __shared__ float2 red1[GPP][32];
    __shared__ float2 red2[GPP][32];

    int tx = threadIdx.x;
    int ty = threadIdx.y;
    int c0 = ty * CPT;

    int h  = blockIdx.x >> 3;            // 8 blocks per row (512/64)
    int w  = ((blockIdx.x & 7) << 6) + 2 * tx;
    int hm = (h - 1) & 511, hp = (h + 1) & 511;
    int b0 = h << 9, bm = hm << 9, bp = hp << 9;
    int wm1 = (w - 1) & 511;
    int wp2 = (w + 2) & 511;
    int pA = b0 + w;

    const float* x  = (ssel == 1) ? (const float*)g_a : (const float*)g_b;
    float* xo       = (ssel == 1) ? g_b : g_a;
    const float* si = (ssel == 1) ? (const float*)g_s0 : (const float*)g_s1;
    float* so       = (ssel == 1) ? g_s1 : g_s0;

    float2 C[12];
    #pragma unroll
    for (int k = 0; k < 12; k++)
        C[k] = *(const float2*)&g_aux[k*NP + pA];

    float2 s2  = *(const float2*)&si[pA];
    float2 sp2 = *(const float2*)&si[bp + w];
    float2 sr2 = *(const float2*)&si[b0 + wp2];
    float dsxA = sp2.x - s2.x, dsxB = sp2.y - s2.y;
    float dsyA = s2.y  - s2.x, dsyB = sr2.x - s2.y;

    float2 val[CPT];
    float2 cen[CPT];
    float vsumA = 0.0f, vsumB = 0.0f;
    #pragma unroll
    for (int c = 0; c < CPT; c++) {
        const float* xc = x + (size_t)(c0 + c) * NP;
        float  Lm = xc[bm + wm1], Rm = xc[bm + wp2];
        float2 Mm = *(const float2*)&xc[bm + w];
        float  L0 = xc[b0 + wm1], R0 = xc[b0 + wp2];
        float2 M0 = *(const float2*)&xc[b0 + w];
        float  Lp = xc[bp + wm1], Rp = xc[bp + wp2];
        float2 Mp = *(const float2*)&xc[bp + w];

        float accA = C[4].x * M0.x;
        accA = fmaf(C[0].x, Lm,   accA);
        accA = fmaf(C[1].x, Mm.x, accA);
        accA = fmaf(C[2].x, Mm.y, accA);
        accA = fmaf(C[3].x, L0,   accA);
        accA = fmaf(C[5].x, M0.y, accA);
        accA = fmaf(C[6].x, Lp,   accA);
        accA = fmaf(C[7].x, Mp.x, accA);
        accA = fmaf(C[8].x, Mp.y, accA);
        float vxA = (Mp.x - M0.x) - dsxA;
        float vyA = (M0.y - M0.x) - dsyA;
        accA = fmaf(fmaf(C[11].x, vyA, C[9].x * vxA), vxA, accA);
        accA = fmaf(C[10].x, vyA * vyA, accA);
        accA = fmaf(0.1f, M0.x, accA);

        float accB = C[4].y * M0.y;
        accB = fmaf(C[0].y, Mm.x, accB);
        accB = fmaf(C[1].y, Mm.y, accB);
        accB = fmaf(C[2].y, Rm,   accB);
        accB = fmaf(C[3].y, M0.x, accB);
        accB = fmaf(C[5].y, R0,   accB);
        accB = fmaf(C[6].y, Mp.x, accB);
        accB = fmaf(C[7].y, Mp.y, accB);
        accB = fmaf(C[8].y, Rp,   accB);
        float vxB = (Mp.y - M0.y) - dsxB;
        float vyB = (R0   - M0.y) - dsyB;
        accB = fmaf(fmaf(C[11].y, vyB, C[9].y * vxB), vxB, accB);
        accB = fmaf(C[10].y, vyB * vyB, accB);
        accB = fmaf(0.1f, M0.y, accB);

        val[c].x = accA; val[c].y = accB;
        cen[c] = M0;
        vsumA += accA; vsumB += accB;
    }

    red0[ty][tx].x = vsumA;
    red0[ty][tx].y = vsumB;
    __syncthreads();
    float meanA = 0.0f, meanB = 0.0f;
    #pragma unroll
    for (int g = 0; g < GPP; g++) {
        meanA += red0[g][tx].x;
        meanB += red0[g][tx].y;
    }
    meanA *= (1.0f / 48.0f);
    meanB *= (1.0f / 48.0f);

    #pragma unroll
    for (int c = 0; c < CPT; c++) {
        float tA = val[c].x - meanA;
        float tB = val[c].y - meanB;
        tA = fminf(fmaxf(tA, -1e8f), 1e8f);
        tB = fminf(fmaxf(tB, -1e8f), 1e8f);
        val[c].x = fmaf(0.2f, tA, cen[c].x);
        val[c].y = fmaf(0.2f, tB, cen[c].y);
    }

    float mA = val[0].x, mB = val[0].y;
    #pragma unroll
    for (int c = 1; c < CPT; c++) {
        mA = fmaxf(mA, val[c].x);
        mB = fmaxf(mB, val[c].y);
    }
    red1[ty][tx].x = mA;
    red1[ty][tx].y = mB;
    #pragma unroll
    for (int c = 0; c < CPT; c++)
        *(float2*)&xo[(size_t)(c0 + c) * NP + pA] = val[c];
    __syncthreads();
    mA = red1[0][tx].x; mB = red1[0][tx].y;
    #pragma unroll
    for (int g = 1; g < GPP; g++) {
        mA = fmaxf(mA, red1[g][tx].x);
        mB = fmaxf(mB, red1[g][tx].y);
    }
    float esA = 0.0f, esB = 0.0f;
    #pragma unroll
    for (int c = 0; c < CPT; c++) {
        esA += __expf(val[c].x - mA);
        esB += __expf(val[c].y - mB);
    }
    red2[ty][tx].x = esA;
    red2[ty][tx].y = esB;
    __syncthreads();
    if (ty == 0) {
        float sumA = 0.0f, sumB = 0.0f;
        #pragma unroll
        for (int g = 0; g < GPP; g++) {
            sumA += red2[g][tx].x;
            sumB += red2[g][tx].y;
        }
        float2 os;
        os.x = mA + __logf(sumA);
        os.y = mB + __logf(sumB);
        *(float2*)&so[pA] = os;
    }
}

// ---- K3: final step — same stencil, smem-staged coalesced interleaved output.
//          No logsumexp epilogue, no planar store. ----
__global__ void __launch_bounds__(32*GPP, 3) k_last(int ssel,
                                                    float* __restrict__ out_ilv) {
    __shared__ float2 red0[GPP][32];
    __shared__ float smo[64*49];     // 64 px x 48 ch staging, pitch 49

    int tx = threadIdx.x;
    int ty = threadIdx.y;
    int c0 = ty * CPT;

    int h  = blockIdx.x >> 3;
    int w  = ((blockIdx.x & 7) << 6) + 2 * tx;
    int hm = (h - 1) & 511, hp = (h + 1) & 511;
    int b0 = h << 9, bm = hm << 9, bp = hp << 9;
    int wm1 = (w - 1) & 511;
    int wp2 = (w + 2) & 511;
    int pA = b0 + w;

    const float* x  = (ssel == 1) ? (const float*)g_a : (const float*)g_b;
    const float* si = (ssel == 1) ? (const float*)g_s0 : (const float*)g_s1;

    float2 C[12];
    #pragma unroll
    for (int k = 0; k < 12; k++)
        C[k] = *(const float2*)&g_aux[k*NP + pA];

    float2 s2  = *(const float2*)&si[pA];
    float2 sp2 = *(const float2*)&si[bp + w];
    float2 sr2 = *(const float2*)&si[b0 + wp2];
    float dsxA = sp2.x - s2.x, dsxB = sp2.y - s2.y;
    float dsyA = s2.y  - s2.x, dsyB = sr2.x - s2.y;

    float2 val[CPT];
    float2 cen[CPT];
    float vsumA = 0.0f, vsumB = 0.0f;
    #pragma unroll
    for (int c = 0; c < CPT; c++) {
        const float* xc = x + (size_t)(c0 + c) * NP;
        float  Lm = xc[bm + wm1], Rm = xc[bm + wp2];
        float2 Mm = *(const float2*)&xc[bm + w];
        float  L0 = xc[b0 + wm1], R0 = xc[b0 + wp2];
        float2 M0 = *(const float2*)&xc[b0 + w];
        float  Lp = xc[bp + wm1], Rp = xc[bp + wp2];
        float2 Mp = *(const float2*)&xc[bp + w];

        float accA = C[4].x * M0.x;
        accA = fmaf(C[0].x, Lm,   accA);
        accA = fmaf(C[1].x, Mm.x, accA);
        accA = fmaf(C[2].x, Mm.y, accA);
        accA = fmaf(C[3].x, L0,   accA);
        accA = fmaf(C[5].x, M0.y, accA);
        accA = fmaf(C[6].x, Lp,   accA);
        accA = fmaf(C[7].x, Mp.x, accA);
        accA = fmaf(C[8].x, Mp.y, accA);
        float vxA = (Mp.x - M0.x) - dsxA;
        float vyA = (M0.y - M0.x) - dsyA;
        accA = fmaf(fmaf(C[11].x, vyA, C[9].x * vxA), vxA, accA);
        accA = fmaf(C[10].x, vyA * vyA, accA);
        accA = fmaf(0.1f, M0.x, accA);

        float accB = C[4].y * M0.y;
        accB = fmaf(C[0].y, Mm.x, accB);
        accB = fmaf(C[1].y, Mm.y, accB);
        accB = fmaf(C[2].y, Rm,   accB);
        accB = fmaf(C[3].y, M0.x, accB);
        accB = fmaf(C[5].y, R0,   accB);
        accB = fmaf(C[6].y, Mp.x, accB);
        accB = fmaf(C[7].y, Mp.y, accB);
        accB = fmaf(C[8].y, Rp,   accB);
        float vxB = (Mp.y - M0.y) - dsxB;
        float vyB = (R0   - M0.y) - dsyB;
        accB = fmaf(fmaf(C[11].y, vyB, C[9].y * vxB), vxB, accB);
        accB = fmaf(C[10].y, vyB * vyB, accB);
        accB = fmaf(0.1f, M0.y, accB);

        val[c].x = accA; val[c].y = accB;
        cen[c] = M0;
        vsumA += accA; vsumB += accB;
    }

    red0[ty][tx].x = vsumA;
    red0[ty][tx].y = vsumB;
    __syncthreads();
    float meanA = 0.0f, meanB = 0.0f;
    #pragma unroll
    for (int g = 0; g < GPP; g++) {
        meanA += red0[g][tx].x;
        meanB += red0[g][tx].y;
    }
    meanA *= (1.0f / 48.0f);
    meanB *= (1.0f / 48.0f);

    // Euler update + stage into smem (pixel-major, pitch 49)
    int pxA = 2 * tx, pxB = 2 * tx + 1;
    #pragma unroll
    for (int c = 0; c < CPT; c++) {
        float tA = val[c].x - meanA;
        float tB = val[c].y - meanB;
        tA = fminf(fmaxf(tA, -1e8f), 1e8f);
        tB = fminf(fmaxf(tB, -1e8f), 1e8f);
        smo[pxA*49 + c0 + c] = fmaf(0.2f, tA, cen[c].x);
        smo[pxB*49 + c0 + c] = fmaf(0.2f, tB, cen[c].y);
    }
    __syncthreads();

    // coalesced interleaved write: 64px x 48ch = 768 float4
    int tid = ty * 32 + tx;
    float4* o4 = (float4*)(out_ilv + (size_t)blockIdx.x * 64 * NC);
    #pragma unroll
    for (int i = 0; i < 3; i++) {
        int f4 = i * 256 + tid;
        int off = f4 * 4;                // 48 % 4 == 0: float4 within one pixel
        int px = off / 48;
        int ch = off % 48;
        const float* s4 = &smo[px*49 + ch];
        float4 t;
        t.x = s4[0]; t.y = s4[1]; t.z = s4[2]; t.w = s4[3];
        o4[f4] = t;
    }
}

extern "C" void kernel_launch(void* const* d_in, const int* in_sizes, int n_in,
                              void* d_out, int out_size) {
    const float* v    = (const float*)d_in[0];
    const float* Dt   = (const float*)d_in[1];
    const float* dg   = (const float*)d_in[2];
    const float* hinv = (const float*)d_in[3];
    float* out = (float*)d_out;

    k_init<<<NP / 64, 256>>>(v, Dt, dg, hinv);

    dim3 blk(32, GPP);
    int grid = NP / PXW;   // 4096
    k_step<<<grid, blk>>>(1);
    k_step<<<grid, blk>>>(2);
    k_step<<<grid, blk>>>(1);
    k_step<<<grid, blk>>>(2);
    k_last<<<grid, blk>>>(1, out);
}